// round 1
// baseline (speedup 1.0000x reference)
#include <cuda_runtime.h>
#include <cstdint>

// ---------------------------------------------------------------------------
// Poly2d: out[b,o,h,w] = sum_c s^T F_{o,c} s + bias[o],  s = [1, 3x3 patch]
// Factorized: 54 features per channel (9 linear + 45 symmetric pairs),
// const term folded into bias. Packed-weight GEMM with fp32x2 FFMA.
// ---------------------------------------------------------------------------

#define NCH   64
#define NOUT  64
#define NFEAT 54
#define WROW  64                 // floats per (c,k) weight row (= NOUT)
#define WCH   (NFEAT * WROW)     // 3456 floats per channel

__device__ __align__(16) float g_Wp[NCH * WCH];   // [c][k][o]
__device__ __align__(16) float g_bias2[NOUT];

// ---------------------------------------------------------------------------
// helpers
// ---------------------------------------------------------------------------
__device__ __forceinline__ uint32_t s2u(const void* p) {
    return (uint32_t)__cvta_generic_to_shared(p);
}
__device__ __forceinline__ void cpa4(void* s, const void* g, bool ok) {
    asm volatile("cp.async.ca.shared.global [%0], [%1], 4, %2;\n"
                 :: "r"(s2u(s)), "l"(g), "r"(ok ? 4 : 0));
}
__device__ __forceinline__ void cpa16(void* s, const void* g) {
    asm volatile("cp.async.cg.shared.global [%0], [%1], 16;\n"
                 :: "r"(s2u(s)), "l"(g));
}
__device__ __forceinline__ long long fma2(long long a, long long b, long long c) {
    long long d;
    asm("fma.rn.f32x2 %0, %1, %2, %3;" : "=l"(d) : "l"(a), "l"(b), "l"(c));
    return d;
}

// ---------------------------------------------------------------------------
// Prep kernel: pack symmetric weights + fold constant term into bias.
//   filters: [64][64][10][10] row-major, biases: [64][1]
//   Wp[c][k][o]:
//     k in [0,9):   linear tap t=k (patch idx), coef = F[0][t+1] + F[t+1][0]
//     k in [9,54):  pairs (i<=j) over taps 0..8, i-outer/j-inner,
//                   coef = F[i+1][j+1] + F[j+1][i+1]   (i<j)
//                        = F[i+1][i+1]                  (i==j)
//   bias2[o] = bias[o] + sum_c F[o][c][0][0]
// ---------------------------------------------------------------------------
__global__ void poly_prep(const float* __restrict__ filters,
                          const float* __restrict__ biases) {
    const int c = blockIdx.x;    // 64
    const int o = threadIdx.x;   // 64
    const float* F = filters + o * 6400 + c * 100;
    float* W = g_Wp + c * WCH + o;
    int k = 0;
    #pragma unroll
    for (int t = 1; t <= 9; ++t) { W[k * WROW] = F[t] + F[t * 10]; ++k; }
    #pragma unroll
    for (int i = 1; i <= 9; ++i)
        #pragma unroll
        for (int j = i; j <= 9; ++j) {
            W[k * WROW] = (i == j) ? F[i * 10 + i] : (F[i * 10 + j] + F[j * 10 + i]);
            ++k;
        }
    if (c == 0) {
        float s = biases[o];
        for (int cc = 0; cc < NCH; ++cc) s += filters[o * 6400 + cc * 100];
        g_bias2[o] = s;
    }
}

// ---------------------------------------------------------------------------
// Main kernel.
// Grid: 256 CTAs = (b, row). Block: 256 threads = 4 o-groups x 64 cols.
// Thread: one pixel (row r, col w), 16 outputs (og*16 .. og*16+15) as
// 8 f32x2 accumulators; loops 64 channels with cp.async double-buffered
// weight (13.8KB) + x-halo (816B) staging.
// ---------------------------------------------------------------------------
__global__ __launch_bounds__(256, 2)
void poly_main(const float* __restrict__ x, float* __restrict__ out) {
    __shared__ __align__(16) float wbuf[2][WCH];       // 27,648 B
    __shared__ __align__(16) float xbuf[2][3][68];     //  1,632 B

    const int b   = blockIdx.x >> 6;
    const int r   = blockIdx.x & 63;
    const int og  = threadIdx.x >> 6;   // 0..3
    const int w   = threadIdx.x & 63;   // pixel col
    const int tid = threadIdx.x;

    long long acc[8];
    {
        const long long* b2 = (const long long*)g_bias2;
        #pragma unroll
        for (int q = 0; q < 8; ++q) acc[q] = b2[og * 8 + q];
    }

    auto stage = [&](int c, int buf) {
        // x halo: 3 rows x 68 cols (col index 0 == w=-1), zero-filled OOB
        if (tid < 204) {
            const int rr = tid / 68, col = tid % 68;
            const int gr = r - 1 + rr, gw = col - 1;
            const bool ok = ((unsigned)gr < 64u) && ((unsigned)gw < 64u);
            const float* src =
                x + (((b * NCH + c) * 64 + (ok ? gr : 0)) * 64 + (ok ? gw : 0));
            cpa4(&xbuf[buf][rr][col], src, ok);
        }
        // weights: 3456 floats = 864 float4
        const float4* srcw = (const float4*)(g_Wp + c * WCH);
        float4* dstw = (float4*)wbuf[buf];
        #pragma unroll
        for (int i = 0; i < 4; ++i) {
            const int idx = tid + i * 256;
            if (idx < WCH / 4) cpa16(dstw + idx, srcw + idx);
        }
    };

    stage(0, 0);
    asm volatile("cp.async.commit_group;\n" ::: "memory");

    for (int c = 0; c < NCH; ++c) {
        __syncthreads();  // prior iter finished reading buf (c+1)&1
        stage((c + 1) & (NCH - 1), (c + 1) & 1);
        asm volatile("cp.async.commit_group;\n" ::: "memory");
        asm volatile("cp.async.wait_group 1;\n" ::: "memory");
        __syncthreads();  // buf c&1 visible to all threads

        const int buf = c & 1;

        // 9 taps around this pixel
        float t[9];
        #pragma unroll
        for (int rr = 0; rr < 3; ++rr)
            #pragma unroll
            for (int dx = 0; dx < 3; ++dx)
                t[rr * 3 + dx] = xbuf[buf][rr][w + dx];

        // 54 features (order must match poly_prep)
        float f[NFEAT];
        {
            int k = 0;
            #pragma unroll
            for (int tt = 0; tt < 9; ++tt) f[k++] = t[tt];
            #pragma unroll
            for (int i = 0; i < 9; ++i)
                #pragma unroll
                for (int j = i; j < 9; ++j) f[k++] = t[i] * t[j];
        }

        // accumulate: per feature, 8 packed-pair FFMA2 over this thread's
        // 16 outputs; weight pairs loaded as LDS.128 (warp-uniform broadcast)
        const float* wrow = wbuf[buf] + og * 16;
        #pragma unroll
        for (int k = 0; k < NFEAT; ++k) {
            long long f2;
            asm("mov.b64 %0, {%1, %1};" : "=l"(f2) : "f"(f[k]));
            const ulonglong2* wp = (const ulonglong2*)(wrow + k * WROW);
            #pragma unroll
            for (int q = 0; q < 4; ++q) {
                ulonglong2 ww = wp[q];
                acc[2 * q]     = fma2(f2, (long long)ww.x, acc[2 * q]);
                acc[2 * q + 1] = fma2(f2, (long long)ww.y, acc[2 * q + 1]);
            }
        }
    }

    // write out: coalesced per output plane
    #pragma unroll
    for (int q = 0; q < 8; ++q) {
        float lo, hi;
        asm("mov.b64 {%0, %1}, %2;" : "=f"(lo), "=f"(hi) : "l"(acc[q]));
        const int o = og * 16 + 2 * q;
        out[(((b * NOUT + o)     * 64 + r) * 64) + w] = lo;
        out[(((b * NOUT + o + 1) * 64 + r) * 64) + w] = hi;
    }
}

// ---------------------------------------------------------------------------
// launch
// ---------------------------------------------------------------------------
extern "C" void kernel_launch(void* const* d_in, const int* in_sizes, int n_in,
                              void* d_out, int out_size) {
    const float* x       = (const float*)d_in[0];  // [4,64,64,64]
    const float* filters = (const float*)d_in[1];  // [64,64,10,10]
    const float* biases  = (const float*)d_in[2];  // [64,1]
    float* out = (float*)d_out;                    // [4,64,64,64]
    (void)in_sizes; (void)n_in; (void)out_size;

    poly_prep<<<64, 64>>>(filters, biases);
    poly_main<<<256, 256>>>(x, out);
}

// round 5
// speedup vs baseline: 4.4425x; 4.4425x over previous
#include <cuda_runtime.h>
#include <cuda_fp16.h>
#include <cstdint>

// ---------------------------------------------------------------------------
// Poly2d via warp-level HMMA (mma.sync m16n8k16, fp16 in / fp32 acc).
//   out[b,o,h,w] = sum_c s^T F_{o,c} s + bias[o],  s = [1, 3x3 patch]
// Factorized: 54 features/channel (9 linear + 45 symmetric pairs) padded to
// 64; const term folded into bias. Per CTA: D[128 px, 64 o] accumulated over
// K = 64 ch x 64 feat.
// ---------------------------------------------------------------------------

#define NCH   64
#define NOUT  64
#define KPAD  64

// per-channel 8KB fp16 weight block, SW128 swizzle PRE-APPLIED so linear
// cp.async yields an ldmatrix-ready [o][k] tile. row o = 128B, k 0..63.
__device__ __align__(16) unsigned short g_W16[NCH * NOUT * KPAD];
__device__ float g_bias2[NOUT];

__device__ __forceinline__ uint32_t s2u(const void* p) {
    return (uint32_t)__cvta_generic_to_shared(p);
}
__device__ __forceinline__ void cpa4(uint32_t s, const void* g, bool ok) {
    asm volatile("cp.async.ca.shared.global [%0], [%1], 4, %2;\n"
                 :: "r"(s), "l"(g), "r"(ok ? 4 : 0));
}
__device__ __forceinline__ void cpa16(uint32_t s, const void* g) {
    asm volatile("cp.async.cg.shared.global [%0], [%1], 16;\n"
                 :: "r"(s), "l"(g));
}
__device__ __forceinline__ uint32_t swz(uint32_t off) {   // SW128
    return off ^ ((off >> 3) & 0x70);
}
__device__ __forceinline__ void ldsm4(uint32_t& r0, uint32_t& r1, uint32_t& r2,
                                      uint32_t& r3, uint32_t addr) {
    asm volatile("ldmatrix.sync.aligned.m8n8.x4.shared.b16 {%0,%1,%2,%3}, [%4];"
                 : "=r"(r0), "=r"(r1), "=r"(r2), "=r"(r3) : "r"(addr));
}
__device__ __forceinline__ void mma16816(float& c0, float& c1, float& c2, float& c3,
                                         uint32_t a0, uint32_t a1, uint32_t a2,
                                         uint32_t a3, uint32_t b0, uint32_t b1) {
    asm volatile(
        "mma.sync.aligned.m16n8k16.row.col.f32.f16.f16.f32 "
        "{%0,%1,%2,%3}, {%4,%5,%6,%7}, {%8,%9}, {%0,%1,%2,%3};"
        : "+f"(c0), "+f"(c1), "+f"(c2), "+f"(c3)
        : "r"(a0), "r"(a1), "r"(a2), "r"(a3), "r"(b0), "r"(b1));
}

// ---------------------------------------------------------------------------
// Prep: pack symmetric weights -> fp16, SW128 pre-applied; fold const term
// into bias. block = channel (64), thread = output o (64).
// ---------------------------------------------------------------------------
__global__ void poly_prep(const float* __restrict__ filters,
                          const float* __restrict__ biases) {
    __shared__ __align__(16) unsigned short wsm[NOUT * KPAD];  // 8KB
    const int c = blockIdx.x, o = threadIdx.x;
    const float* F = filters + o * 6400 + c * 100;

    float v[KPAD];
    int k = 0;
    #pragma unroll
    for (int t = 1; t <= 9; ++t) v[k++] = F[t] + F[t * 10];
    #pragma unroll
    for (int i = 1; i <= 9; ++i)
        #pragma unroll
        for (int j = i; j <= 9; ++j)
            v[k++] = (i == j) ? F[i * 10 + i] : (F[i * 10 + j] + F[j * 10 + i]);
    #pragma unroll
    for (; k < KPAD; ++k) v[k] = 0.0f;

    #pragma unroll
    for (int kk = 0; kk < KPAD; ++kk)
        wsm[swz((uint32_t)(o * 128 + kk * 2)) >> 1] =
            __half_as_ushort(__float2half_rn(v[kk]));
    __syncthreads();
    uint4* dst = (uint4*)(g_W16 + c * NOUT * KPAD);
    const uint4* srcp = (const uint4*)wsm;
    for (int i = o; i < 512; i += 64) dst[i] = srcp[i];

    if (c == 0) {
        float s = biases[o];
        for (int cc = 0; cc < NCH; ++cc) s += filters[o * 6400 + cc * 100];
        g_bias2[o] = s;
    }
}

// ---------------------------------------------------------------------------
// Main kernel: 128 CTAs (b, row-pair) x 256 threads (8 warps).
// Warp grid 4x2: warp covers m rows [mrow*32,+32), o cols [ncol*32,+32).
// Feature gen: thread = pixel (tid&127) x k-half (tid>>7).
// ---------------------------------------------------------------------------
__global__ void __launch_bounds__(256, 1)
poly_mma(const float* __restrict__ x, float* __restrict__ out) {
    __shared__ __align__(16) unsigned short Asm[128 * KPAD];       // 16KB
    __shared__ __align__(16) unsigned short Bsm[2][NOUT * KPAD];   // 16KB
    __shared__ __align__(16) float xsm[2][4 * 68];                 // 2176B

    const int tid = threadIdx.x, lane = tid & 31, wid = tid >> 5;
    const int m = tid & 127, h = tid >> 7;
    const int ry = m >> 6, wcol = m & 63;
    const int mrow = wid >> 1, ncol = wid & 1;
    const int b = blockIdx.x >> 5;
    const int r0 = (blockIdx.x & 31) * 2;

    const uint32_t Abase = s2u(Asm);
    const uint32_t Bbase0 = s2u(Bsm[0]);

    float acc[2][4][4];
    #pragma unroll
    for (int mt = 0; mt < 2; ++mt)
        #pragma unroll
        for (int n8 = 0; n8 < 4; ++n8)
            #pragma unroll
            for (int q = 0; q < 4; ++q) acc[mt][n8][q] = 0.0f;

    auto stage = [&](int c) {
        const int buf = c & 1;
        #pragma unroll
        for (int i = tid; i < 272; i += 256) {       // 4 x 68 halo, col0 == w-1
            const int rr = i / 68, col = i % 68;
            const int gr = r0 - 1 + rr, gw = col - 1;
            const bool ok = ((unsigned)gr < 64u) && ((unsigned)gw < 64u);
            const float* src =
                x + (((b * NCH + c) * 64 + (ok ? gr : 0)) * 64 + (ok ? gw : 0));
            cpa4(s2u(&xsm[buf][rr * 68 + col]), src, ok);
        }
        const uint4* srcw = (const uint4*)(g_W16 + c * NOUT * KPAD);
        #pragma unroll
        for (int i = tid; i < 512; i += 256)
            cpa16(s2u(Bsm[buf]) + (uint32_t)i * 16, srcw + i);
    };

    stage(0);
    asm volatile("cp.async.commit_group;" ::: "memory");

    // precompute ldmatrix lane addresses (swizzled offsets, per k-step base)
    // A: row = mrow*32 + mt*16 + (lane&15), chunk = (lane>>4)*16
    // B: row = ncol*32 + nt*16 + (lane&15), chunk = (lane>>4)*16
    uint32_t a_off[2], b_off[2];
    #pragma unroll
    for (int mt = 0; mt < 2; ++mt)
        a_off[mt] = (uint32_t)((mrow * 32 + mt * 16 + (lane & 15)) * 128 +
                               (lane >> 4) * 16);
    #pragma unroll
    for (int nt = 0; nt < 2; ++nt)
        b_off[nt] = (uint32_t)((ncol * 32 + nt * 16 + (lane & 15)) * 128 +
                               (lane >> 4) * 16);

    for (int c = 0; c < NCH; ++c) {
        asm volatile("cp.async.wait_group 0;" ::: "memory");
        __syncthreads();                         // x[c], B[c] visible
        if (c + 1 < NCH) stage(c + 1);
        asm volatile("cp.async.commit_group;" ::: "memory");

        // ---- features for this pixel/half ----
        const float* xbp = xsm[c & 1];
        float t[9];
        #pragma unroll
        for (int rr = 0; rr < 3; ++rr)
            #pragma unroll
            for (int dx = 0; dx < 3; ++dx)
                t[rr * 3 + dx] = xbp[(ry + rr) * 68 + wcol + dx];

        float fl[32];
        if (h == 0) {
            #pragma unroll
            for (int tt = 0; tt < 9; ++tt) fl[tt] = t[tt];
            int k = 9;
            #pragma unroll
            for (int i = 0; i < 9; ++i)
                #pragma unroll
                for (int j = i; j < 9; ++j) {
                    if (k < 32) fl[k] = t[i] * t[j];
                    ++k;
                }
        } else {
            int k = 9;
            #pragma unroll
            for (int i = 0; i < 9; ++i)
                #pragma unroll
                for (int j = i; j < 9; ++j) {
                    if (k >= 32 && k < 54) fl[k - 32] = t[i] * t[j];
                    ++k;
                }
            #pragma unroll
            for (int z = 22; z < 32; ++z) fl[z] = 0.0f;
        }

        #pragma unroll
        for (int q = 0; q < 4; ++q) {            // 16B chunks into SW128 A
            uint32_t r[4];
            #pragma unroll
            for (int u = 0; u < 4; ++u) {
                __half2 hh = __floats2half2_rn(fl[q * 8 + 2 * u],
                                               fl[q * 8 + 2 * u + 1]);
                r[u] = *reinterpret_cast<uint32_t*>(&hh);
            }
            uint32_t off = swz((uint32_t)(m * 128 + h * 64 + q * 16));
            asm volatile("st.shared.v4.b32 [%0], {%1,%2,%3,%4};"
                         :: "r"(Abase + off), "r"(r[0]), "r"(r[1]), "r"(r[2]),
                            "r"(r[3]) : "memory");
        }
        __syncthreads();                         // A tile ready

        // ---- HMMA over K = 64 ----
        const uint32_t Bb = Bbase0 + (uint32_t)(c & 1) * (NOUT * KPAD * 2);
        #pragma unroll
        for (int ks = 0; ks < 4; ++ks) {
            const uint32_t kadd = (uint32_t)ks * 32;
            uint32_t a0[4], a1[4], bA[4], bB[4];
            ldsm4(a0[0], a0[1], a0[2], a0[3], Abase + swz(a_off[0] + kadd));
            ldsm4(a1[0], a1[1], a1[2], a1[3], Abase + swz(a_off[1] + kadd));
            ldsm4(bA[0], bA[1], bA[2], bA[3], Bb + swz(b_off[0] + kadd));
            ldsm4(bB[0], bB[1], bB[2], bB[3], Bb + swz(b_off[1] + kadd));

            mma16816(acc[0][0][0], acc[0][0][1], acc[0][0][2], acc[0][0][3],
                     a0[0], a0[1], a0[2], a0[3], bA[0], bA[2]);
            mma16816(acc[0][1][0], acc[0][1][1], acc[0][1][2], acc[0][1][3],
                     a0[0], a0[1], a0[2], a0[3], bA[1], bA[3]);
            mma16816(acc[0][2][0], acc[0][2][1], acc[0][2][2], acc[0][2][3],
                     a0[0], a0[1], a0[2], a0[3], bB[0], bB[2]);
            mma16816(acc[0][3][0], acc[0][3][1], acc[0][3][2], acc[0][3][3],
                     a0[0], a0[1], a0[2], a0[3], bB[1], bB[3]);
            mma16816(acc[1][0][0], acc[1][0][1], acc[1][0][2], acc[1][0][3],
                     a1[0], a1[1], a1[2], a1[3], bA[0], bA[2]);
            mma16816(acc[1][1][0], acc[1][1][1], acc[1][1][2], acc[1][1][3],
                     a1[0], a1[1], a1[2], a1[3], bA[1], bA[3]);
            mma16816(acc[1][2][0], acc[1][2][1], acc[1][2][2], acc[1][2][3],
                     a1[0], a1[1], a1[2], a1[3], bB[0], bB[2]);
            mma16816(acc[1][3][0], acc[1][3][1], acc[1][3][2], acc[1][3][3],
                     a1[0], a1[1], a1[2], a1[3], bB[1], bB[3]);
        }
    }

    // ---- epilogue: c-frag -> global, + bias ----
    const int obase = ncol * 32 + (lane & 3) * 2;
    float2 bias2v[4];
    #pragma unroll
    for (int n8 = 0; n8 < 4; ++n8)
        bias2v[n8] = *(const float2*)(g_bias2 + obase + n8 * 8);

    #pragma unroll
    for (int mt = 0; mt < 2; ++mt) {
        #pragma unroll
        for (int half = 0; half < 2; ++half) {
            const int mm = mrow * 32 + mt * 16 + (lane >> 2) + half * 8;
            const int rr = r0 + (mm >> 6), cc = mm & 63;
            float* op = out + ((b * NOUT) * 64 + rr) * 64 + cc;
            #pragma unroll
            for (int n8 = 0; n8 < 4; ++n8) {
                const int o = obase + n8 * 8;
                op[(o)     * 4096] = acc[mt][n8][half * 2]     + bias2v[n8].x;
                op[(o + 1) * 4096] = acc[mt][n8][half * 2 + 1] + bias2v[n8].y;
            }
        }
    }
}

// ---------------------------------------------------------------------------
extern "C" void kernel_launch(void* const* d_in, const int* in_sizes, int n_in,
                              void* d_out, int out_size) {
    const float* x       = (const float*)d_in[0];  // [4,64,64,64]
    const float* filters = (const float*)d_in[1];  // [64,64,10,10]
    const float* biases  = (const float*)d_in[2];  // [64,1]
    float* out = (float*)d_out;                    // [4,64,64,64]
    (void)in_sizes; (void)n_in; (void)out_size;

    poly_prep<<<64, 64>>>(filters, biases);
    poly_mma<<<128, 256>>>(x, out);
}

// round 6
// speedup vs baseline: 4.5714x; 1.0290x over previous
#include <cuda_runtime.h>
#include <cuda_fp16.h>
#include <cstdint>

// ---------------------------------------------------------------------------
// Poly2d via warp-level HMMA (mma.sync m16n8k16, fp16 in / fp32 acc).
// Factorized: 54 features/channel (9 linear + 45 symmetric pairs) padded to
// 64; const term folded into bias. Round 6: 2 channels per mainloop iter
// (K=128 per phase), double-buffered A so one featgen/MMA barrier pair
// covers 2 channels -> longer HMMA bursts, half the barriers.
// ---------------------------------------------------------------------------

#define NCH   64
#define NOUT  64
#define KPAD  64

__device__ __align__(16) unsigned short g_W16[NCH * NOUT * KPAD];
__device__ float g_bias2[NOUT];

// dynamic smem layout (bytes)
#define OFF_A   0                         // 2 buf x (2 blocks x 16384) = 65536
#define OFF_B   65536                     // 2 buf x (2 blocks x 8192)  = 32768
#define OFF_X   (OFF_B + 32768)           // 2 buf x 2 ch x 272 floats  = 4352
#define SMEM_SZ (OFF_X + 4352)

__device__ __forceinline__ uint32_t s2u(const void* p) {
    return (uint32_t)__cvta_generic_to_shared(p);
}
__device__ __forceinline__ void cpa4(uint32_t s, const void* g, bool ok) {
    asm volatile("cp.async.ca.shared.global [%0], [%1], 4, %2;\n"
                 :: "r"(s), "l"(g), "r"(ok ? 4 : 0));
}
__device__ __forceinline__ void cpa16(uint32_t s, const void* g) {
    asm volatile("cp.async.cg.shared.global [%0], [%1], 16;\n"
                 :: "r"(s), "l"(g));
}
__device__ __forceinline__ uint32_t swz(uint32_t off) {   // SW128
    return off ^ ((off >> 3) & 0x70);
}
__device__ __forceinline__ void ldsm4(uint32_t& r0, uint32_t& r1, uint32_t& r2,
                                      uint32_t& r3, uint32_t addr) {
    asm volatile("ldmatrix.sync.aligned.m8n8.x4.shared.b16 {%0,%1,%2,%3}, [%4];"
                 : "=r"(r0), "=r"(r1), "=r"(r2), "=r"(r3) : "r"(addr));
}
__device__ __forceinline__ void mma16816(float& c0, float& c1, float& c2, float& c3,
                                         uint32_t a0, uint32_t a1, uint32_t a2,
                                         uint32_t a3, uint32_t b0, uint32_t b1) {
    asm volatile(
        "mma.sync.aligned.m16n8k16.row.col.f32.f16.f16.f32 "
        "{%0,%1,%2,%3}, {%4,%5,%6,%7}, {%8,%9}, {%0,%1,%2,%3};"
        : "+f"(c0), "+f"(c1), "+f"(c2), "+f"(c3)
        : "r"(a0), "r"(a1), "r"(a2), "r"(a3), "r"(b0), "r"(b1));
}

// ---------------------------------------------------------------------------
// Prep: pack symmetric weights -> fp16, SW128 pre-applied; fold const term
// into bias. block = channel (64), thread = output o (64).
// ---------------------------------------------------------------------------
__global__ void poly_prep(const float* __restrict__ filters,
                          const float* __restrict__ biases) {
    __shared__ __align__(16) unsigned short wsm[NOUT * KPAD];
    const int c = blockIdx.x, o = threadIdx.x;
    const float* F = filters + o * 6400 + c * 100;

    float v[KPAD];
    int k = 0;
    #pragma unroll
    for (int t = 1; t <= 9; ++t) v[k++] = F[t] + F[t * 10];
    #pragma unroll
    for (int i = 1; i <= 9; ++i)
        #pragma unroll
        for (int j = i; j <= 9; ++j)
            v[k++] = (i == j) ? F[i * 10 + i] : (F[i * 10 + j] + F[j * 10 + i]);
    #pragma unroll
    for (; k < KPAD; ++k) v[k] = 0.0f;

    #pragma unroll
    for (int kk = 0; kk < KPAD; ++kk)
        wsm[swz((uint32_t)(o * 128 + kk * 2)) >> 1] =
            __half_as_ushort(__float2half_rn(v[kk]));
    __syncthreads();
    uint4* dst = (uint4*)(g_W16 + c * NOUT * KPAD);
    const uint4* srcp = (const uint4*)wsm;
    for (int i = o; i < 512; i += 64) dst[i] = srcp[i];

    if (c == 0) {
        float s = biases[o];
        for (int cc = 0; cc < NCH; ++cc) s += filters[o * 6400 + cc * 100];
        g_bias2[o] = s;
    }
}

// ---------------------------------------------------------------------------
// Main kernel: 128 CTAs (b, row-pair) x 256 threads (8 warps).
// Warp grid 4x2 over D[128 px, 64 o]; mainloop iter = 2 channels (K=128).
// ---------------------------------------------------------------------------
extern __shared__ unsigned char smdyn[];

__global__ void __launch_bounds__(256, 1)
poly_mma(const float* __restrict__ x, float* __restrict__ out) {
    const uint32_t smb = s2u(smdyn);
    const int tid = threadIdx.x, lane = tid & 31, wid = tid >> 5;
    const int m = tid & 127, h = tid >> 7;
    const int ry = m >> 6, wcol = m & 63;
    const int mrow = wid >> 1, ncol = wid & 1;
    const int b = blockIdx.x >> 5;
    const int r0 = (blockIdx.x & 31) * 2;

    float acc[2][4][4];
    #pragma unroll
    for (int mt = 0; mt < 2; ++mt)
        #pragma unroll
        for (int n8 = 0; n8 < 4; ++n8)
            #pragma unroll
            for (int q = 0; q < 4; ++q) acc[mt][n8][q] = 0.0f;

    // stage channel pair (2j, 2j+1) into buffer j&1
    auto stage = [&](int j) {
        const uint32_t buf = (uint32_t)(j & 1);
        #pragma unroll
        for (int i = tid; i < 544; i += 256) {     // 2 ch x 4 rows x 68 cols
            const int p = i / 272, rem = i % 272;
            const int rr = rem / 68, col = rem % 68;
            const int gr = r0 - 1 + rr, gw = col - 1;
            const bool ok = ((unsigned)gr < 64u) && ((unsigned)gw < 64u);
            const int c = 2 * j + p;
            const float* src =
                x + (((b * NCH + c) * 64 + (ok ? gr : 0)) * 64 + (ok ? gw : 0));
            cpa4(smb + OFF_X + (uint32_t)(buf * 544 + i) * 4, src, ok);
        }
        const uint4* srcw = (const uint4*)(g_W16 + (2 * j) * NOUT * KPAD);
        #pragma unroll
        for (int i = tid; i < 1024; i += 256)      // 2 ch x 8KB
            cpa16(smb + OFF_B + buf * 16384 + (uint32_t)i * 16, srcw + i);
    };

    stage(0);
    asm volatile("cp.async.commit_group;" ::: "memory");

    // ldmatrix lane offsets within a 16KB (A) / 8KB (B) SW128 block
    uint32_t a_off[2], b_off[2];
    #pragma unroll
    for (int mt = 0; mt < 2; ++mt)
        a_off[mt] = (uint32_t)((mrow * 32 + mt * 16 + (lane & 15)) * 128 +
                               (lane >> 4) * 16);
    #pragma unroll
    for (int nt = 0; nt < 2; ++nt)
        b_off[nt] = (uint32_t)((ncol * 32 + nt * 16 + (lane & 15)) * 128 +
                               (lane >> 4) * 16);

    for (int j = 0; j < NCH / 2; ++j) {
        asm volatile("cp.async.wait_group 0;" ::: "memory");
        __syncthreads();   // x[j], B[j] ready; all MMA(j-2) complete (via j-1's
                           // second barrier) so A[j&1] is reusable

        if (j + 1 < NCH / 2) stage(j + 1);
        asm volatile("cp.async.commit_group;" ::: "memory");

        const uint32_t abuf = smb + OFF_A + (uint32_t)(j & 1) * 32768;
        const uint32_t bbuf = smb + OFF_B + (uint32_t)(j & 1) * 16384;

        // ---- features for both channels of this pair ----
        #pragma unroll
        for (int p = 0; p < 2; ++p) {
            const float* xbp =
                (const float*)(smdyn + OFF_X) + (j & 1) * 544 + p * 272;
            float t[9];
            #pragma unroll
            for (int rr = 0; rr < 3; ++rr)
                #pragma unroll
                for (int dx = 0; dx < 3; ++dx)
                    t[rr * 3 + dx] = xbp[(ry + rr) * 68 + wcol + dx];

            float fl[32];
            if (h == 0) {
                #pragma unroll
                for (int tt = 0; tt < 9; ++tt) fl[tt] = t[tt];
                int k = 9;
                #pragma unroll
                for (int i = 0; i < 9; ++i)
                    #pragma unroll
                    for (int jj = i; jj < 9; ++jj) {
                        if (k < 32) fl[k] = t[i] * t[jj];
                        ++k;
                    }
            } else {
                int k = 9;
                #pragma unroll
                for (int i = 0; i < 9; ++i)
                    #pragma unroll
                    for (int jj = i; jj < 9; ++jj) {
                        if (k >= 32 && k < 54) fl[k - 32] = t[i] * t[jj];
                        ++k;
                    }
                #pragma unroll
                for (int z = 22; z < 32; ++z) fl[z] = 0.0f;
            }

            #pragma unroll
            for (int q = 0; q < 4; ++q) {
                uint32_t r[4];
                #pragma unroll
                for (int u = 0; u < 4; ++u) {
                    __half2 hh = __floats2half2_rn(fl[q * 8 + 2 * u],
                                                   fl[q * 8 + 2 * u + 1]);
                    r[u] = *reinterpret_cast<uint32_t*>(&hh);
                }
                uint32_t off = swz((uint32_t)(m * 128 + h * 64 + q * 16));
                asm volatile("st.shared.v4.b32 [%0], {%1,%2,%3,%4};"
                             :: "r"(abuf + (uint32_t)p * 16384 + off),
                                "r"(r[0]), "r"(r[1]), "r"(r[2]), "r"(r[3])
                             : "memory");
            }
        }
        __syncthreads();   // A pair ready

        // ---- HMMA over K = 128 (8 k-steps, 2 channel blocks) ----
        #pragma unroll
        for (int ks = 0; ks < 8; ++ks) {
            const uint32_t kh = (uint32_t)(ks >> 2);
            const uint32_t kl = (uint32_t)(ks & 3) * 32;
            const uint32_t Ab = abuf + kh * 16384;
            const uint32_t Bb = bbuf + kh * 8192;
            uint32_t a0[4], a1[4], bA[4], bB[4];
            ldsm4(a0[0], a0[1], a0[2], a0[3], Ab + swz(a_off[0] + kl));
            ldsm4(a1[0], a1[1], a1[2], a1[3], Ab + swz(a_off[1] + kl));
            ldsm4(bA[0], bA[1], bA[2], bA[3], Bb + swz(b_off[0] + kl));
            ldsm4(bB[0], bB[1], bB[2], bB[3], Bb + swz(b_off[1] + kl));

            mma16816(acc[0][0][0], acc[0][0][1], acc[0][0][2], acc[0][0][3],
                     a0[0], a0[1], a0[2], a0[3], bA[0], bA[2]);
            mma16816(acc[0][1][0], acc[0][1][1], acc[0][1][2], acc[0][1][3],
                     a0[0], a0[1], a0[2], a0[3], bA[1], bA[3]);
            mma16816(acc[0][2][0], acc[0][2][1], acc[0][2][2], acc[0][2][3],
                     a0[0], a0[1], a0[2], a0[3], bB[0], bB[2]);
            mma16816(acc[0][3][0], acc[0][3][1], acc[0][3][2], acc[0][3][3],
                     a0[0], a0[1], a0[2], a0[3], bB[1], bB[3]);
            mma16816(acc[1][0][0], acc[1][0][1], acc[1][0][2], acc[1][0][3],
                     a1[0], a1[1], a1[2], a1[3], bA[0], bA[2]);
            mma16816(acc[1][1][0], acc[1][1][1], acc[1][1][2], acc[1][1][3],
                     a1[0], a1[1], a1[2], a1[3], bA[1], bA[3]);
            mma16816(acc[1][2][0], acc[1][2][1], acc[1][2][2], acc[1][2][3],
                     a1[0], a1[1], a1[2], a1[3], bB[0], bB[2]);
            mma16816(acc[1][3][0], acc[1][3][1], acc[1][3][2], acc[1][3][3],
                     a1[0], a1[1], a1[2], a1[3], bB[1], bB[3]);
        }
    }

    // ---- epilogue: c-frag -> global, + bias ----
    const int obase = ncol * 32 + (lane & 3) * 2;
    float2 bias2v[4];
    #pragma unroll
    for (int n8 = 0; n8 < 4; ++n8)
        bias2v[n8] = *(const float2*)(g_bias2 + obase + n8 * 8);

    #pragma unroll
    for (int mt = 0; mt < 2; ++mt) {
        #pragma unroll
        for (int half = 0; half < 2; ++half) {
            const int mm = mrow * 32 + mt * 16 + (lane >> 2) + half * 8;
            const int rr = r0 + (mm >> 6), cc = mm & 63;
            float* op = out + ((b * NOUT) * 64 + rr) * 64 + cc;
            #pragma unroll
            for (int n8 = 0; n8 < 4; ++n8) {
                const int o = obase + n8 * 8;
                op[(o)     * 4096] = acc[mt][n8][half * 2]     + bias2v[n8].x;
                op[(o + 1) * 4096] = acc[mt][n8][half * 2 + 1] + bias2v[n8].y;
            }
        }
    }
}

// ---------------------------------------------------------------------------
extern "C" void kernel_launch(void* const* d_in, const int* in_sizes, int n_in,
                              void* d_out, int out_size) {
    const float* x       = (const float*)d_in[0];  // [4,64,64,64]
    const float* filters = (const float*)d_in[1];  // [64,64,10,10]
    const float* biases  = (const float*)d_in[2];  // [64,1]
    float* out = (float*)d_out;                    // [4,64,64,64]
    (void)in_sizes; (void)n_in; (void)out_size;

    static int attr_set = 0;
    if (!attr_set) {
        cudaFuncSetAttribute(poly_mma,
                             cudaFuncAttributeMaxDynamicSharedMemorySize,
                             SMEM_SZ);
        attr_set = 1;
    }
    poly_prep<<<64, 64>>>(filters, biases);
    poly_mma<<<128, 256, SMEM_SZ>>>(x, out);
}